// round 1
// baseline (speedup 1.0000x reference)
#include <cuda_runtime.h>
#include <math.h>

#define NB 32
#define WTOT 202112

// Scratch (device globals — no allocations allowed)
__device__ float g_y[NB * WTOT];          // generated per-sample conv weights, ~25.9 MB
__device__ float g_A[NB * 1048576];       // ping buffer, 128 MB (max per-sample plane set = 1M floats)
__device__ float g_B[NB * 1048576];       // pong buffer, 128 MB
__device__ float g_stats[NB * 64 * 2];    // per-(b,c) BN scale/shift

// ---------------------------------------------------------------------------
// Weight generation: y[s][r] = W[r,:] @ a[s,:] + b[r], one thread per row r,
// loops all 32 samples with the W row held in registers (W read exactly once).
// ---------------------------------------------------------------------------
__global__ void gen_weights(const float* __restrict__ W, const float* __restrict__ bias,
                            const float* __restrict__ act, int rows, int off) {
    __shared__ float sa[NB * 32];
    for (int i = threadIdx.x; i < NB * 32; i += blockDim.x) sa[i] = act[i];
    __syncthreads();
    int r = blockIdx.x * blockDim.x + threadIdx.x;
    if (r >= rows) return;
    float w[32];
    const float4* wp = reinterpret_cast<const float4*>(W + (size_t)r * 32);
#pragma unroll
    for (int i = 0; i < 8; i++) {
        float4 v = wp[i];
        w[4*i+0] = v.x; w[4*i+1] = v.y; w[4*i+2] = v.z; w[4*i+3] = v.w;
    }
    float bv = bias[r];
    for (int s = 0; s < NB; s++) {
        float acc = bv;
#pragma unroll
        for (int k = 0; k < 32; k++) acc = fmaf(w[k], sa[s*32+k], acc);
        g_y[(size_t)s * WTOT + off + r] = acc;
    }
}

// ---------------------------------------------------------------------------
// BN stats: one block per (b,c) plane. Produces scale = g*rsqrt(var+eps),
// shift = be - mean*scale  (training-mode BN, biased variance).
// ---------------------------------------------------------------------------
__global__ void bn_stats(const float* __restrict__ src, const float* __restrict__ g,
                         const float* __restrict__ be, int C, int HW) {
    int plane = blockIdx.x;                  // b*C + c
    int c = plane % C;
    const float* p = src + (size_t)plane * HW;
    float s = 0.f, s2 = 0.f;
    for (int i = threadIdx.x; i < HW; i += 256) { float v = p[i]; s += v; s2 = fmaf(v, v, s2); }
    __shared__ float sh0[256], sh1[256];
    sh0[threadIdx.x] = s; sh1[threadIdx.x] = s2;
    __syncthreads();
    for (int ofs = 128; ofs > 0; ofs >>= 1) {
        if (threadIdx.x < ofs) {
            sh0[threadIdx.x] += sh0[threadIdx.x + ofs];
            sh1[threadIdx.x] += sh1[threadIdx.x + ofs];
        }
        __syncthreads();
    }
    if (threadIdx.x == 0) {
        float inv = 1.f / (float)HW;
        float m = sh0[0] * inv;
        float var = sh1[0] * inv - m * m;
        float sc = g[c] * rsqrtf(var + 1e-5f);
        g_stats[plane*2]   = sc;
        g_stats[plane*2+1] = be[c] - m * sc;
    }
}

// ---------------------------------------------------------------------------
// Direct 5x5 conv (stride 1, "same"), dilation DIL in {1,2}, pad = 2*DIL.
// MODE: input transform applied on tile load (BN folded into the consumer):
//   0 = identity, 1 = scale/shift, 2 = scale/shift + relu.
// Block: 16x16 threads; 32x32 output tile, 4 pixels/thread (stride-16 split),
// 16 output channels per block (all convs have Cout in {16,32,64}).
// Smem pitch RS=48 keeps tap loads bank-conflict-free across half-warps.
// ---------------------------------------------------------------------------
template<int DIL, int MODE>
__global__ __launch_bounds__(256)
void conv5x5(const float* __restrict__ in, float* __restrict__ out,
             int Cin, int S, int wOff, int grps) {
    constexpr int PAD = 2 * DIL;
    constexpr int TIN = 32 + 4 * DIL;        // 36 (dil1) or 40 (dil2)
    constexpr int RS  = 48;
    __shared__ float sm[TIN * RS];
    __shared__ float sw[16 * 25];
    int z = blockIdx.z;
    int b = z / grps, gq = z - b * grps;
    int gbase = gq * 16;
    int x0 = blockIdx.x * 32, y0 = blockIdx.y * 32;
    int tx = threadIdx.x, ty = threadIdx.y;
    int tid = ty * 16 + tx;
    float acc[4][16];
#pragma unroll
    for (int p = 0; p < 4; p++)
#pragma unroll
        for (int gg = 0; gg < 16; gg++) acc[p][gg] = 0.f;
    const float* wb = g_y + (size_t)b * WTOT + wOff;

    for (int c = 0; c < Cin; c++) {
        float sc = 1.f, sf = 0.f;
        if (MODE) { sc = g_stats[(b*Cin+c)*2]; sf = g_stats[(b*Cin+c)*2+1]; }
        const float* ip = in + ((size_t)(b * Cin + c)) * S * S;
        // load input tile with transform + zero padding
        for (int i = tid; i < TIN * TIN; i += 256) {
            int r = i / TIN, col = i - r * TIN;
            int iy = y0 - PAD + r, ix = x0 - PAD + col;
            float v = 0.f;
            if (iy >= 0 && iy < S && ix >= 0 && ix < S) {
                v = ip[(size_t)iy * S + ix];
                if (MODE) { v = fmaf(v, sc, sf); if (MODE == 2) v = fmaxf(v, 0.f); }
            }
            sm[r * RS + col] = v;
        }
        // load 16 x 25 weight slice for this cin
        for (int i = tid; i < 400; i += 256) {
            int gg = i / 25, k = i - gg * 25;
            sw[i] = wb[((size_t)(gbase + gg) * Cin + c) * 25 + k];
        }
        __syncthreads();
#pragma unroll 1
        for (int ky = 0; ky < 5; ky++) {
#pragma unroll
            for (int kx = 0; kx < 5; kx++) {
                int base = (ty + ky * DIL) * RS + tx + kx * DIL;
                float t0 = sm[base];
                float t1 = sm[base + 16];
                float t2 = sm[base + 16 * RS];
                float t3 = sm[base + 16 * RS + 16];
                int wk = ky * 5 + kx;
#pragma unroll
                for (int gg = 0; gg < 16; gg++) {
                    float w = sw[gg * 25 + wk];     // broadcast LDS
                    acc[0][gg] = fmaf(t0, w, acc[0][gg]);
                    acc[1][gg] = fmaf(t1, w, acc[1][gg]);
                    acc[2][gg] = fmaf(t2, w, acc[2][gg]);
                    acc[3][gg] = fmaf(t3, w, acc[3][gg]);
                }
            }
        }
        __syncthreads();
    }
    int Cout = grps * 16;
#pragma unroll
    for (int gg = 0; gg < 16; gg++) {
        float* op = out + ((size_t)(b * Cout + gbase + gg)) * S * S;
        op[(size_t)(y0 + ty) * S + x0 + tx]           = acc[0][gg];
        op[(size_t)(y0 + ty) * S + x0 + tx + 16]      = acc[1][gg];
        op[(size_t)(y0 + ty + 16) * S + x0 + tx]      = acc[2][gg];
        op[(size_t)(y0 + ty + 16) * S + x0 + tx + 16] = acc[3][gg];
    }
}

// ---------------------------------------------------------------------------
// 2x2 avg-pool fused with BN-apply (affine commutes with mean).
// in: raw conv2 output (32,16,256,256); out: (32,16,128,128).
// ---------------------------------------------------------------------------
__global__ void pool_bn(const float* __restrict__ in, float* __restrict__ out) {
    int idx = blockIdx.x * blockDim.x + threadIdx.x;
    if (idx >= NB * 16 * 128 * 128) return;
    int x = idx & 127, y = (idx >> 7) & 127, pc = idx >> 14;   // pc = b*16 + c
    const float* ip = in + (size_t)pc * 65536;
    int o2 = (2 * y) * 256 + 2 * x;
    float v = (ip[o2] + ip[o2+1] + ip[o2+256] + ip[o2+257]) * 0.25f;
    out[idx] = fmaf(v, g_stats[pc*2], g_stats[pc*2+1]);
}

// ---------------------------------------------------------------------------
// 1x1 conv (64 -> 8) with BN(stats6) folded into input. in: raw conv6 output.
// ---------------------------------------------------------------------------
__global__ void conv1x1(const float* __restrict__ in, float* __restrict__ out) {
    __shared__ float sw[512];
    int b = blockIdx.y;
    const float* wb = g_y + (size_t)b * WTOT + 201600;
    for (int i = threadIdx.x; i < 512; i += blockDim.x) sw[i] = wb[i];
    __syncthreads();
    int pix = blockIdx.x * blockDim.x + threadIdx.x;
    if (pix >= 16384) return;
    float acc[8] = {0,0,0,0,0,0,0,0};
    for (int c = 0; c < 64; c++) {
        float v = in[((size_t)(b*64 + c)) * 16384 + pix];
        v = fmaf(v, g_stats[(b*64+c)*2], g_stats[(b*64+c)*2+1]);
#pragma unroll
        for (int o = 0; o < 8; o++) acc[o] = fmaf(v, sw[o*64 + c], acc[o]);
    }
#pragma unroll
    for (int o = 0; o < 8; o++) out[((size_t)(b*8 + o)) * 16384 + pix] = acc[o];
}

// ---------------------------------------------------------------------------
// Bilinear x2 upsample (align_corners=True) + channel softmax (C=8).
// ---------------------------------------------------------------------------
__global__ void up_softmax(const float* __restrict__ in, float* __restrict__ out) {
    int idx = blockIdx.x * blockDim.x + threadIdx.x;
    if (idx >= NB * 65536) return;
    int x = idx & 255, y = (idx >> 8) & 255, b = idx >> 16;
    const float r = 127.0f / 255.0f;
    float sy = y * r, sx = x * r;
    int y0 = (int)sy, x0 = (int)sx;
    int y1 = min(y0 + 1, 127), x1 = min(x0 + 1, 127);
    float wy = sy - (float)y0, wx = sx - (float)x0;
    const float* bp = in + (size_t)b * 8 * 16384;
    float v[8], m = -1e30f;
#pragma unroll
    for (int o = 0; o < 8; o++) {
        const float* p = bp + o * 16384;
        float a00 = p[y0*128+x0], a01 = p[y0*128+x1];
        float a10 = p[y1*128+x0], a11 = p[y1*128+x1];
        float t0 = a00 * (1.f - wy) + a10 * wy;     // y-interp first (match ref order)
        float t1 = a01 * (1.f - wy) + a11 * wy;
        v[o] = t0 * (1.f - wx) + t1 * wx;
        m = fmaxf(m, v[o]);
    }
    float s = 0.f;
#pragma unroll
    for (int o = 0; o < 8; o++) { v[o] = expf(v[o] - m); s += v[o]; }
    float invs = 1.f / s;
    size_t base = ((size_t)b * 8) * 65536 + (size_t)y * 256 + x;
#pragma unroll
    for (int o = 0; o < 8; o++) out[base + (size_t)o * 65536] = v[o] * invs;
}

// ---------------------------------------------------------------------------
extern "C" void kernel_launch(void* const* d_in, const int* in_sizes, int n_in,
                              void* d_out, int out_size) {
    const float* x   = (const float*)d_in[0];
    const float* act = (const float*)d_in[1];
    const float* g[7]; const float* be[7];
    for (int i = 0; i < 7; i++) {
        g[i]  = (const float*)d_in[16 + 2*i];
        be[i] = (const float*)d_in[17 + 2*i];
    }
    float* out = (float*)d_out;
    float *pA = nullptr, *pB = nullptr;
    cudaGetSymbolAddress((void**)&pA, g_A);
    cudaGetSymbolAddress((void**)&pB, g_B);

    const int rows[7] = {3200, 6400, 12800, 25600, 51200, 102400, 512};
    const int offs[7] = {0, 3200, 9600, 22400, 48000, 99200, 201600};
    for (int i = 0; i < 7; i++) {
        gen_weights<<<(rows[i] + 255) / 256, 256>>>(
            (const float*)d_in[2 + 2*i], (const float*)d_in[3 + 2*i], act, rows[i], offs[i]);
    }

    // bn0 on x, then conv1 (dil2, Cin8->16, 256^2), BN folded into conv input
    bn_stats<<<NB * 8, 256>>>(x, g[0], be[0], 8, 65536);
    conv5x5<2, 1><<<dim3(8, 8, NB * 1), dim3(16, 16)>>>(x,  pA, 8,  256, offs[0], 1);
    bn_stats<<<NB * 16, 256>>>(pA, g[1], be[1], 16, 65536);
    conv5x5<1, 2><<<dim3(8, 8, NB * 1), dim3(16, 16)>>>(pA, pB, 16, 256, offs[1], 1);
    bn_stats<<<NB * 16, 256>>>(pB, g[2], be[2], 16, 65536);
    pool_bn<<<(NB * 16 * 16384 + 255) / 256, 256>>>(pB, pA);
    conv5x5<2, 0><<<dim3(4, 4, NB * 2), dim3(16, 16)>>>(pA, pB, 16, 128, offs[2], 2);
    bn_stats<<<NB * 32, 256>>>(pB, g[3], be[3], 32, 16384);
    conv5x5<1, 2><<<dim3(4, 4, NB * 2), dim3(16, 16)>>>(pB, pA, 32, 128, offs[3], 2);
    bn_stats<<<NB * 32, 256>>>(pA, g[4], be[4], 32, 16384);
    conv5x5<2, 1><<<dim3(4, 4, NB * 4), dim3(16, 16)>>>(pA, pB, 32, 128, offs[4], 4);
    bn_stats<<<NB * 64, 256>>>(pB, g[5], be[5], 64, 16384);
    conv5x5<1, 2><<<dim3(4, 4, NB * 4), dim3(16, 16)>>>(pB, pA, 64, 128, offs[5], 4);
    bn_stats<<<NB * 64, 256>>>(pA, g[6], be[6], 64, 16384);
    conv1x1<<<dim3(64, NB), 256>>>(pA, pB);
    up_softmax<<<(NB * 65536 + 255) / 256, 256>>>(pB, out);
}

// round 2
// speedup vs baseline: 1.1928x; 1.1928x over previous
#include <cuda_runtime.h>
#include <math.h>

#define NB 32
#define WTOT 202112

// Scratch (device globals — no allocations allowed)
__device__ float g_y[NB * WTOT];          // generated per-sample conv weights, ~25.9 MB
__device__ float g_A[NB * 1048576];       // ping buffer, 128 MB
__device__ float g_B[NB * 1048576];       // pong buffer, 128 MB
__device__ float g_stats[NB * 64 * 2];    // per-(b,c) BN scale/shift

// ---- packed f32x2 helpers (FFMA2 only reachable via PTX) -------------------
__device__ __forceinline__ unsigned long long pack2(float lo, float hi) {
    unsigned long long r;
    asm("mov.b64 %0, {%1, %2};" : "=l"(r) : "f"(lo), "f"(hi));
    return r;
}
__device__ __forceinline__ void ffma2(unsigned long long& d,
                                      unsigned long long a, unsigned long long b) {
    asm("fma.rn.f32x2 %0, %1, %2, %0;" : "+l"(d) : "l"(a), "l"(b));
}
__device__ __forceinline__ void unpack2(unsigned long long v, float& lo, float& hi) {
    asm("mov.b64 {%0, %1}, %2;" : "=f"(lo), "=f"(hi) : "l"(v));
}

// ---------------------------------------------------------------------------
// Weight generation: y[s][r] = W[r,:] @ a[s,:] + b[r]
// ---------------------------------------------------------------------------
__global__ void gen_weights(const float* __restrict__ W, const float* __restrict__ bias,
                            const float* __restrict__ act, int rows, int off) {
    __shared__ float sa[NB * 32];
    for (int i = threadIdx.x; i < NB * 32; i += blockDim.x) sa[i] = act[i];
    __syncthreads();
    int r = blockIdx.x * blockDim.x + threadIdx.x;
    if (r >= rows) return;
    float w[32];
    const float4* wp = reinterpret_cast<const float4*>(W + (size_t)r * 32);
#pragma unroll
    for (int i = 0; i < 8; i++) {
        float4 v = wp[i];
        w[4*i+0] = v.x; w[4*i+1] = v.y; w[4*i+2] = v.z; w[4*i+3] = v.w;
    }
    float bv = bias[r];
    for (int s = 0; s < NB; s++) {
        float acc = bv;
#pragma unroll
        for (int k = 0; k < 32; k++) acc = fmaf(w[k], sa[s*32+k], acc);
        g_y[(size_t)s * WTOT + off + r] = acc;
    }
}

// ---------------------------------------------------------------------------
// BN stats: one block per (b,c) plane -> scale = g*rsqrt(var+eps),
// shift = be - mean*scale (training-mode BN, biased variance).
// ---------------------------------------------------------------------------
__global__ void bn_stats(const float* __restrict__ src, const float* __restrict__ g,
                         const float* __restrict__ be, int C, int HW) {
    int plane = blockIdx.x;
    int c = plane % C;
    const float* p = src + (size_t)plane * HW;
    float s = 0.f, s2 = 0.f;
    for (int i = threadIdx.x; i < HW; i += 256) { float v = p[i]; s += v; s2 = fmaf(v, v, s2); }
    __shared__ float sh0[256], sh1[256];
    sh0[threadIdx.x] = s; sh1[threadIdx.x] = s2;
    __syncthreads();
    for (int ofs = 128; ofs > 0; ofs >>= 1) {
        if (threadIdx.x < ofs) {
            sh0[threadIdx.x] += sh0[threadIdx.x + ofs];
            sh1[threadIdx.x] += sh1[threadIdx.x + ofs];
        }
        __syncthreads();
    }
    if (threadIdx.x == 0) {
        float inv = 1.f / (float)HW;
        float m = sh0[0] * inv;
        float var = sh1[0] * inv - m * m;
        float sc = g[c] * rsqrtf(var + 1e-5f);
        g_stats[plane*2]   = sc;
        g_stats[plane*2+1] = be[c] - m * sc;
    }
}

// ---------------------------------------------------------------------------
// Direct 5x5 conv, dilation DIL, pad = 2*DIL, BN(+relu) folded into tile load.
// 32x32 output tile / 16 channels per block; packed FFMA2 inner loop:
// acc paired across adjacent output channels, weight pairs via broadcast LDS.64.
// ---------------------------------------------------------------------------
template<int DIL, int MODE>
__global__ __launch_bounds__(256)
void conv5x5(const float* __restrict__ in, float* __restrict__ out,
             int Cin, int S, int wOff, int grps) {
    constexpr int PAD = 2 * DIL;
    constexpr int TIN = 32 + 4 * DIL;
    constexpr int RS  = 48;
    __shared__ float sm[TIN * RS];
    __shared__ __align__(8) float sw[25 * 16];    // [wk][gg] layout
    int z = blockIdx.z;
    int b = z / grps, gq = z - b * grps;
    int gbase = gq * 16;
    int x0 = blockIdx.x * 32, y0 = blockIdx.y * 32;
    int tx = threadIdx.x, ty = threadIdx.y;
    int tid = ty * 16 + tx;
    unsigned long long acc[4][8];
#pragma unroll
    for (int p = 0; p < 4; p++)
#pragma unroll
        for (int j = 0; j < 8; j++) acc[p][j] = 0ULL;
    const float* wb = g_y + (size_t)b * WTOT + wOff;

    for (int c = 0; c < Cin; c++) {
        float sc = 1.f, sf = 0.f;
        if (MODE) { sc = g_stats[(b*Cin+c)*2]; sf = g_stats[(b*Cin+c)*2+1]; }
        const float* ip = in + ((size_t)(b * Cin + c)) * S * S;
        for (int i = tid; i < TIN * TIN; i += 256) {
            int r = i / TIN, col = i - r * TIN;
            int iy = y0 - PAD + r, ix = x0 - PAD + col;
            float v = 0.f;
            if (iy >= 0 && iy < S && ix >= 0 && ix < S) {
                v = ip[(size_t)iy * S + ix];
                if (MODE) { v = fmaf(v, sc, sf); if (MODE == 2) v = fmaxf(v, 0.f); }
            }
            sm[r * RS + col] = v;
        }
        // weights: sw[k*16 + gg]
        for (int i = tid; i < 400; i += 256) {
            int k = i >> 4, gg = i & 15;
            sw[i] = wb[((size_t)(gbase + gg) * Cin + c) * 25 + k];
        }
        __syncthreads();
#pragma unroll 1
        for (int ky = 0; ky < 5; ky++) {
#pragma unroll
            for (int kx = 0; kx < 5; kx++) {
                int base = (ty + ky * DIL) * RS + tx + kx * DIL;
                unsigned long long T0 = pack2(sm[base],                sm[base]);
                unsigned long long T1 = pack2(sm[base + 16],           sm[base + 16]);
                unsigned long long T2 = pack2(sm[base + 16*RS],        sm[base + 16*RS]);
                unsigned long long T3 = pack2(sm[base + 16*RS + 16],   sm[base + 16*RS + 16]);
                const unsigned long long* wq =
                    reinterpret_cast<const unsigned long long*>(sw + (ky * 5 + kx) * 16);
#pragma unroll
                for (int j = 0; j < 8; j++) {
                    unsigned long long w2 = wq[j];     // broadcast LDS.64: (w[2j], w[2j+1])
                    ffma2(acc[0][j], T0, w2);
                    ffma2(acc[1][j], T1, w2);
                    ffma2(acc[2][j], T2, w2);
                    ffma2(acc[3][j], T3, w2);
                }
            }
        }
        __syncthreads();
    }
    int Cout = grps * 16;
#pragma unroll
    for (int j = 0; j < 8; j++) {
        float e0, e1;
        float* op0 = out + ((size_t)(b * Cout + gbase + 2*j)) * S * S;
        float* op1 = op0 + (size_t)S * S;
        size_t o00 = (size_t)(y0 + ty) * S + x0 + tx;
        size_t o10 = (size_t)(y0 + ty + 16) * S + x0 + tx;
        unpack2(acc[0][j], e0, e1); op0[o00]      = e0; op1[o00]      = e1;
        unpack2(acc[1][j], e0, e1); op0[o00 + 16] = e0; op1[o00 + 16] = e1;
        unpack2(acc[2][j], e0, e1); op0[o10]      = e0; op1[o10]      = e1;
        unpack2(acc[3][j], e0, e1); op0[o10 + 16] = e0; op1[o10 + 16] = e1;
    }
}

// ---------------------------------------------------------------------------
// 2x2 avg-pool fused with BN-apply (affine commutes with mean).
// ---------------------------------------------------------------------------
__global__ void pool_bn(const float* __restrict__ in, float* __restrict__ out) {
    int idx = blockIdx.x * blockDim.x + threadIdx.x;
    if (idx >= NB * 16 * 128 * 128) return;
    int x = idx & 127, y = (idx >> 7) & 127, pc = idx >> 14;
    const float* ip = in + (size_t)pc * 65536;
    int o2 = (2 * y) * 256 + 2 * x;
    float v = (ip[o2] + ip[o2+1] + ip[o2+256] + ip[o2+257]) * 0.25f;
    out[idx] = fmaf(v, g_stats[pc*2], g_stats[pc*2+1]);
}

// ---------------------------------------------------------------------------
// 1x1 conv (64 -> 8) with BN(stats6) folded into input.
// ---------------------------------------------------------------------------
__global__ void conv1x1(const float* __restrict__ in, float* __restrict__ out) {
    __shared__ float sw[512];
    int b = blockIdx.y;
    const float* wb = g_y + (size_t)b * WTOT + 201600;
    for (int i = threadIdx.x; i < 512; i += blockDim.x) sw[i] = wb[i];
    __syncthreads();
    int pix = blockIdx.x * blockDim.x + threadIdx.x;
    if (pix >= 16384) return;
    float acc[8] = {0,0,0,0,0,0,0,0};
    for (int c = 0; c < 64; c++) {
        float v = in[((size_t)(b*64 + c)) * 16384 + pix];
        v = fmaf(v, g_stats[(b*64+c)*2], g_stats[(b*64+c)*2+1]);
#pragma unroll
        for (int o = 0; o < 8; o++) acc[o] = fmaf(v, sw[o*64 + c], acc[o]);
    }
#pragma unroll
    for (int o = 0; o < 8; o++) out[((size_t)(b*8 + o)) * 16384 + pix] = acc[o];
}

// ---------------------------------------------------------------------------
// Bilinear x2 upsample (align_corners=True) + channel softmax (C=8).
// ---------------------------------------------------------------------------
__global__ void up_softmax(const float* __restrict__ in, float* __restrict__ out) {
    int idx = blockIdx.x * blockDim.x + threadIdx.x;
    if (idx >= NB * 65536) return;
    int x = idx & 255, y = (idx >> 8) & 255, b = idx >> 16;
    const float r = 127.0f / 255.0f;
    float sy = y * r, sx = x * r;
    int y0 = (int)sy, x0 = (int)sx;
    int y1 = min(y0 + 1, 127), x1 = min(x0 + 1, 127);
    float wy = sy - (float)y0, wx = sx - (float)x0;
    const float* bp = in + (size_t)b * 8 * 16384;
    float v[8], m = -1e30f;
#pragma unroll
    for (int o = 0; o < 8; o++) {
        const float* p = bp + o * 16384;
        float a00 = p[y0*128+x0], a01 = p[y0*128+x1];
        float a10 = p[y1*128+x0], a11 = p[y1*128+x1];
        float t0 = a00 * (1.f - wy) + a10 * wy;
        float t1 = a01 * (1.f - wy) + a11 * wy;
        v[o] = t0 * (1.f - wx) + t1 * wx;
        m = fmaxf(m, v[o]);
    }
    float s = 0.f;
#pragma unroll
    for (int o = 0; o < 8; o++) { v[o] = expf(v[o] - m); s += v[o]; }
    float invs = 1.f / s;
    size_t base = ((size_t)b * 8) * 65536 + (size_t)y * 256 + x;
#pragma unroll
    for (int o = 0; o < 8; o++) out[base + (size_t)o * 65536] = v[o] * invs;
}

// ---------------------------------------------------------------------------
extern "C" void kernel_launch(void* const* d_in, const int* in_sizes, int n_in,
                              void* d_out, int out_size) {
    const float* x   = (const float*)d_in[0];
    const float* act = (const float*)d_in[1];
    const float* g[7]; const float* be[7];
    for (int i = 0; i < 7; i++) {
        g[i]  = (const float*)d_in[16 + 2*i];
        be[i] = (const float*)d_in[17 + 2*i];
    }
    float* out = (float*)d_out;
    float *pA = nullptr, *pB = nullptr;
    cudaGetSymbolAddress((void**)&pA, g_A);
    cudaGetSymbolAddress((void**)&pB, g_B);

    const int rows[7] = {3200, 6400, 12800, 25600, 51200, 102400, 512};
    const int offs[7] = {0, 3200, 9600, 22400, 48000, 99200, 201600};
    for (int i = 0; i < 7; i++) {
        gen_weights<<<(rows[i] + 255) / 256, 256>>>(
            (const float*)d_in[2 + 2*i], (const float*)d_in[3 + 2*i], act, rows[i], offs[i]);
    }

    bn_stats<<<NB * 8, 256>>>(x, g[0], be[0], 8, 65536);
    conv5x5<2, 1><<<dim3(8, 8, NB * 1), dim3(16, 16)>>>(x,  pA, 8,  256, offs[0], 1);
    bn_stats<<<NB * 16, 256>>>(pA, g[1], be[1], 16, 65536);
    conv5x5<1, 2><<<dim3(8, 8, NB * 1), dim3(16, 16)>>>(pA, pB, 16, 256, offs[1], 1);
    bn_stats<<<NB * 16, 256>>>(pB, g[2], be[2], 16, 65536);
    pool_bn<<<(NB * 16 * 16384 + 255) / 256, 256>>>(pB, pA);
    conv5x5<2, 0><<<dim3(4, 4, NB * 2), dim3(16, 16)>>>(pA, pB, 16, 128, offs[2], 2);
    bn_stats<<<NB * 32, 256>>>(pB, g[3], be[3], 32, 16384);
    conv5x5<1, 2><<<dim3(4, 4, NB * 2), dim3(16, 16)>>>(pB, pA, 32, 128, offs[3], 2);
    bn_stats<<<NB * 32, 256>>>(pA, g[4], be[4], 32, 16384);
    conv5x5<2, 1><<<dim3(4, 4, NB * 4), dim3(16, 16)>>>(pA, pB, 32, 128, offs[4], 4);
    bn_stats<<<NB * 64, 256>>>(pB, g[5], be[5], 64, 16384);
    conv5x5<1, 2><<<dim3(4, 4, NB * 4), dim3(16, 16)>>>(pB, pA, 64, 128, offs[5], 4);
    bn_stats<<<NB * 64, 256>>>(pA, g[6], be[6], 64, 16384);
    conv1x1<<<dim3(64, NB), 256>>>(pA, pB);
    up_softmax<<<(NB * 65536 + 255) / 256, 256>>>(pB, out);
}